// round 4
// baseline (speedup 1.0000x reference)
#include <cuda_runtime.h>
#include <cuda_fp16.h>

// Inputs (harness upcasts f16 arrays to f32):
//   x:      [N=16384, DIM=4096] f32 (f16-valued)
//   pairs:  [KROT=8, DIM]       int32 (same local pattern tiled per 128-group)
//   theta:  [KROT, DIM/2]       f32 (f16-valued)
//   scales: [1, DIM]            f32 (f16-valued)
//   out:    [N, DIM]            f32
// Reference rounds to f16 after EVERY op -> *_rn intrinsics (no HFMA2 contraction).
// Bit-exact vs reference confirmed in Round 3 (rel_err = 0.0).
#define DIMV   4096
#define KROT   8
#define NPAIR  2048
#define GRP    128
#define NGRP   32
#define ILG    64
#define ROWS   4       // one warp owns 4 rows x 4096 channels, zero block syncs

// g_cs layout: [k][il*32 + g] -> lane (=group) reads one coalesced 128B line.
__device__ __half2  g_cs[KROT * NPAIR];
__device__ unsigned g_ab[KROT * ILG];

struct __align__(8) H4 { __half2 r01, r23; };   // 4 rows of one channel

// Slot map: slot(c, g) = c*32 + (g ^ (c>>2)).
// Rotation phase:   c uniform, lanes = g        -> banks distinct (XOR const).
// Transpose phases: g uniform, c = 4*lane + j   -> c>>2 = lane -> banks distinct.
__device__ __forceinline__ int slot(int c, int g) {
    return (c << 5) + (g ^ (c >> 2));
}

__global__ void prep_kernel(const float* __restrict__ theta,
                            const int* __restrict__ pairs) {
    int idx = blockIdx.x * blockDim.x + threadIdx.x;
    if (idx < KROT * NPAIR) {
        int k  = idx >> 11;
        int i  = idx & (NPAIR - 1);
        int g  = i >> 6;
        int il = i & (ILG - 1);
        float t = theta[idx];
        __half c = __float2half(cosf(t));
        __half s = __float2half(sinf(t));
        g_cs[(k << 11) + (il << 5) + g] = __halves2half2(c, s);
    }
    if (idx < KROT * ILG) {
        int k  = idx >> 6;
        int il = idx & (ILG - 1);
        int a = pairs[k * DIMV + 2 * il];   // local (0..127), same for all groups
        int b = pairs[k * DIMV + 2 * il + 1];
        g_ab[idx] = (unsigned)(a | (b << 8));
    }
}

__global__ void __launch_bounds__(32)
rot_kernel(const float* __restrict__ x,
           const float* __restrict__ scales,
           float* __restrict__ out) {
    __shared__ H4 s[DIMV];                 // 32KB private warp tile
    const int l = threadIdx.x;             // lane = group during rotation
    const size_t base = (size_t)blockIdx.x * (ROWS * DIMV);

    // ---- Load + transpose: lane l covers channels 4l..4l+3 of each group m ----
    #pragma unroll 4
    for (int m = 0; m < NGRP; m++) {
        const float* p = x + base + m * GRP + 4 * l;
        float4 v0 = *(const float4*)(p);
        float4 v1 = *(const float4*)(p + DIMV);
        float4 v2 = *(const float4*)(p + 2 * DIMV);
        float4 v3 = *(const float4*)(p + 3 * DIMV);
        const float* f0 = &v0.x; const float* f1 = &v1.x;
        const float* f2 = &v2.x; const float* f3 = &v3.x;
        int sb = slot(4 * l, m);           // consecutive j -> +32 slots, same bank
        #pragma unroll
        for (int j = 0; j < 4; j++) {
            H4 w;
            w.r01 = __floats2half2_rn(f0[j], f1[j]);   // exact (inputs f16-valued)
            w.r23 = __floats2half2_rn(f2[j], f3[j]);
            s[sb + (j << 5)] = w;
        }
    }
    __syncwarp();

    // ---- 8 rotation layers: lane-private group, NO synchronization at all ----
    #pragma unroll
    for (int k = 0; k < KROT; k++) {
        #pragma unroll 4
        for (int il = 0; il < ILG; il++) {
            unsigned ab = g_ab[(k << 6) + il];             // warp-uniform
            __half2 cs = g_cs[(k << 11) + (il << 5) + l];  // coalesced 128B, L2-hot
            int a = ab & 255, b = (ab >> 8) & 255;
            int wa = slot(a, l), wb = slot(b, l);
            H4 ua = s[wa], ub = s[wb];                     // LDS.64, conflict-free
            __half2 hc = __half2half2(__low2half(cs));
            __half2 hs = __half2half2(__high2half(cs));
            H4 ra, rb;
            // Per-op f16 rounding, contraction forbidden, reference order.
            ra.r01 = __hsub2_rn(__hmul2_rn(hc, ua.r01), __hmul2_rn(hs, ub.r01));
            rb.r01 = __hadd2_rn(__hmul2_rn(hs, ua.r01), __hmul2_rn(hc, ub.r01));
            ra.r23 = __hsub2_rn(__hmul2_rn(hc, ua.r23), __hmul2_rn(hs, ub.r23));
            rb.r23 = __hadd2_rn(__hmul2_rn(hs, ua.r23), __hmul2_rn(hc, ub.r23));
            s[wa] = ra; s[wb] = rb;                        // STS.64, conflict-free
        }
        // no sync: next layer's channels for group l are written by lane l itself
    }
    __syncwarp();

    // ---- Scale + transpose back + store (coalesced float4 per row) ----
    #pragma unroll 4
    for (int m = 0; m < NGRP; m++) {
        float4 sc4 = *(const float4*)(scales + m * GRP + 4 * l);
        const float* ps = &sc4.x;
        int sb = slot(4 * l, m);
        float4 o0, o1, o2, o3;
        float* q0 = &o0.x; float* q1 = &o1.x;
        float* q2 = &o2.x; float* q3 = &o3.x;
        #pragma unroll
        for (int j = 0; j < 4; j++) {
            H4 w = s[sb + (j << 5)];
            __half2 sc2 = __half2half2(__float2half(ps[j]));  // exact
            __half2 p01 = __hmul2_rn(w.r01, sc2);
            __half2 p23 = __hmul2_rn(w.r23, sc2);
            q0[j] = __half2float(__low2half (p01));
            q1[j] = __half2float(__high2half(p01));
            q2[j] = __half2float(__low2half (p23));
            q3[j] = __half2float(__high2half(p23));
        }
        float* q = out + base + m * GRP + 4 * l;
        *(float4*)(q)            = o0;
        *(float4*)(q + DIMV)     = o1;
        *(float4*)(q + 2 * DIMV) = o2;
        *(float4*)(q + 3 * DIMV) = o3;
    }
}

extern "C" void kernel_launch(void* const* d_in, const int* in_sizes, int n_in,
                              void* d_out, int out_size) {
    const float* x      = (const float*)d_in[0];
    const int*   pairs  = (const int*)d_in[1];
    const float* theta  = (const float*)d_in[2];
    const float* scales = (const float*)d_in[3];
    (void)n_in;

    int N = in_sizes[0] / DIMV;   // 16384

    prep_kernel<<<(KROT * NPAIR + 255) / 256, 256>>>(theta, pairs);
    rot_kernel<<<N / ROWS, 32>>>(x, scales, (float*)d_out);
    (void)out_size;
}

// round 5
// speedup vs baseline: 3.0684x; 3.0684x over previous
#include <cuda_runtime.h>
#include <cuda_fp16.h>

// Inputs (harness upcasts f16 arrays to f32):
//   x:      [N=16384, DIM=4096] f32 (f16-valued)
//   pairs:  [KROT=8, DIM]       int32 (same local pattern tiled per 128-group)
//   theta:  [KROT, DIM/2]       f32 (f16-valued)
//   scales: [1, DIM]            f32 (f16-valued)
//   out:    [N, DIM]            f32
// Reference rounds to f16 after EVERY op -> *_rn intrinsics (no HFMA2 contraction).
// Bit-exact vs reference confirmed in Round 3 (rel_err = 0.0).
#define DIMV   4096
#define KROT   8
#define NPAIR  2048
#define GRP    128
#define NGRP   32
#define ILG    64
#define ROWS   8        // 8 rows per block, packed 16B per channel (LDS.128)
#define TPB    512

// g_cs layout: [k][il*32 + g] -> lanes (=group) read one coalesced 128B line.
__device__ __half2  g_cs[KROT * NPAIR];
__device__ unsigned g_ab[KROT * ILG];

struct __align__(16) H8 { __half2 r01, r23, r45, r67; };  // 8 rows of one channel

// slot(c,g) = c*32 + (g ^ (c>>2)).
// Rotation phase:  c uniform, lanes span g     -> banks 4*((g^x) mod 8) distinct.
// Transpose phase: g uniform, lanes span c>>2  -> banks 4*((g^lane) mod 8) distinct.
__device__ __forceinline__ int slot(int c, int g) {
    return (c << 5) + (g ^ (c >> 2));
}

__global__ void prep_kernel(const float* __restrict__ theta,
                            const int* __restrict__ pairs) {
    int idx = blockIdx.x * blockDim.x + threadIdx.x;
    if (idx < KROT * NPAIR) {
        int k  = idx >> 11;
        int i  = idx & (NPAIR - 1);
        int g  = i >> 6;
        int il = i & (ILG - 1);
        float t = theta[idx];
        __half c = __float2half(cosf(t));
        __half s = __float2half(sinf(t));
        g_cs[(k << 11) + (il << 5) + g] = __halves2half2(c, s);
    }
    if (idx < KROT * ILG) {
        int k  = idx >> 6;
        int il = idx & (ILG - 1);
        int a = pairs[k * DIMV + 2 * il];   // local (0..127), same for all groups
        int b = pairs[k * DIMV + 2 * il + 1];
        g_ab[idx] = (unsigned)(a | (b << 8));
    }
}

__global__ void __launch_bounds__(TPB)
rot_kernel(const float* __restrict__ x,
           const float* __restrict__ scales,
           float* __restrict__ out) {
    extern __shared__ H8 s[];               // 4096 * 16B = 64KB
    const int tid = threadIdx.x;
    const size_t base = (size_t)blockIdx.x * (ROWS * DIMV);

    // ---- Load + transpose: thread covers 2 channel-quads, all 8 rows each ----
    #pragma unroll
    for (int qi = 0; qi < 2; qi++) {
        int q = tid + qi * TPB;              // channel quad 0..1023
        int g = q >> 5;
        int c0 = (q & 31) * 4;               // local channel base
        const float* p = x + base + g * GRP + c0;
        float4 v0 = *(const float4*)(p);
        float4 v1 = *(const float4*)(p + DIMV);
        float4 v2 = *(const float4*)(p + 2 * DIMV);
        float4 v3 = *(const float4*)(p + 3 * DIMV);
        float4 v4 = *(const float4*)(p + 4 * DIMV);
        float4 v5 = *(const float4*)(p + 5 * DIMV);
        float4 v6 = *(const float4*)(p + 6 * DIMV);
        float4 v7 = *(const float4*)(p + 7 * DIMV);
        const float* f0 = &v0.x; const float* f1 = &v1.x;
        const float* f2 = &v2.x; const float* f3 = &v3.x;
        const float* f4 = &v4.x; const float* f5 = &v5.x;
        const float* f6 = &v6.x; const float* f7 = &v7.x;
        #pragma unroll
        for (int j = 0; j < 4; j++) {
            H8 w;
            w.r01 = __floats2half2_rn(f0[j], f1[j]);   // exact: inputs f16-valued
            w.r23 = __floats2half2_rn(f2[j], f3[j]);
            w.r45 = __floats2half2_rn(f4[j], f5[j]);
            w.r67 = __floats2half2_rn(f6[j], f7[j]);
            s[slot(c0 + j, g)] = w;                    // STS.128, conflict-free
        }
    }
    __syncthreads();

    // ---- 8 rotation layers: lanes = 32 groups, 16 warps span il; 4 pairs/thread ----
    const int g = tid & 31;
    const int ilb = tid >> 5;                // 0..15

    #pragma unroll
    for (int k = 0; k < KROT; k++) {
        #pragma unroll
        for (int step = 0; step < 4; step++) {
            int il = ilb + (step << 4);
            unsigned ab = g_ab[(k << 6) + il];             // warp-uniform
            __half2 cs = g_cs[(k << 11) + (il << 5) + g];  // coalesced 128B line
            int a = ab & 255, b = (ab >> 8) & 255;
            int wa = slot(a, g), wb = slot(b, g);
            H8 ua = s[wa], ub = s[wb];                     // LDS.128 x2, conflict-free
            __half2 hc = __half2half2(__low2half(cs));
            __half2 hs = __half2half2(__high2half(cs));
            H8 ra, rb;
            // Per-op f16 rounding, contraction forbidden, reference order.
            ra.r01 = __hsub2_rn(__hmul2_rn(hc, ua.r01), __hmul2_rn(hs, ub.r01));
            rb.r01 = __hadd2_rn(__hmul2_rn(hs, ua.r01), __hmul2_rn(hc, ub.r01));
            ra.r23 = __hsub2_rn(__hmul2_rn(hc, ua.r23), __hmul2_rn(hs, ub.r23));
            rb.r23 = __hadd2_rn(__hmul2_rn(hs, ua.r23), __hmul2_rn(hc, ub.r23));
            ra.r45 = __hsub2_rn(__hmul2_rn(hc, ua.r45), __hmul2_rn(hs, ub.r45));
            rb.r45 = __hadd2_rn(__hmul2_rn(hs, ua.r45), __hmul2_rn(hc, ub.r45));
            ra.r67 = __hsub2_rn(__hmul2_rn(hc, ua.r67), __hmul2_rn(hs, ub.r67));
            rb.r67 = __hadd2_rn(__hmul2_rn(hs, ua.r67), __hmul2_rn(hc, ub.r67));
            s[wa] = ra; s[wb] = rb;                        // STS.128 x2
        }
        __syncthreads();   // pairs disjoint within a layer; sync only between layers
    }

    // ---- Scale + transpose back + store (coalesced float4 per row) ----
    #pragma unroll
    for (int qi = 0; qi < 2; qi++) {
        int q = tid + qi * TPB;
        int gg = q >> 5;
        int c0 = (q & 31) * 4;
        int d = gg * GRP + c0;
        float4 sc4 = *(const float4*)(scales + d);
        const float* ps = &sc4.x;
        float o[ROWS][4];
        #pragma unroll
        for (int j = 0; j < 4; j++) {
            H8 w = s[slot(c0 + j, gg)];                    // LDS.128, conflict-free
            __half2 sc2 = __half2half2(__float2half(ps[j]));  // exact
            __half2 p01 = __hmul2_rn(w.r01, sc2);
            __half2 p23 = __hmul2_rn(w.r23, sc2);
            __half2 p45 = __hmul2_rn(w.r45, sc2);
            __half2 p67 = __hmul2_rn(w.r67, sc2);
            o[0][j] = __half2float(__low2half (p01));
            o[1][j] = __half2float(__high2half(p01));
            o[2][j] = __half2float(__low2half (p23));
            o[3][j] = __half2float(__high2half(p23));
            o[4][j] = __half2float(__low2half (p45));
            o[5][j] = __half2float(__high2half(p45));
            o[6][j] = __half2float(__low2half (p67));
            o[7][j] = __half2float(__high2half(p67));
        }
        float* qp = out + base + d;
        #pragma unroll
        for (int r = 0; r < ROWS; r++) {
            *(float4*)(qp + r * DIMV) = make_float4(o[r][0], o[r][1], o[r][2], o[r][3]);
        }
    }
}

extern "C" void kernel_launch(void* const* d_in, const int* in_sizes, int n_in,
                              void* d_out, int out_size) {
    const float* x      = (const float*)d_in[0];
    const int*   pairs  = (const int*)d_in[1];
    const float* theta  = (const float*)d_in[2];
    const float* scales = (const float*)d_in[3];
    (void)n_in;

    int N = in_sizes[0] / DIMV;   // 16384
    const int smem = DIMV * (int)sizeof(H8);   // 64KB dynamic

    cudaFuncSetAttribute(rot_kernel, cudaFuncAttributeMaxDynamicSharedMemorySize, smem);

    prep_kernel<<<(KROT * NPAIR + 255) / 256, 256>>>(theta, pairs);
    rot_kernel<<<N / ROWS, TPB, smem>>>(x, scales, (float*)d_out);
    (void)out_size;
}